// round 10
// baseline (speedup 1.0000x reference)
#include <cuda_runtime.h>
#include <cuda_fp16.h>
#include <cstdint>
#include <cstddef>

static constexpr int SEQ = 8192;
static constexpr int DM  = 2048;

// ---------------- static device scratch (allocation-free) ----------------
__device__ __align__(256) __half g_Xh[(size_t)SEQ * DM];
__device__ __align__(256) __half g_Wq[(size_t)DM * DM];
__device__ __align__(256) __half g_Wk[(size_t)DM * DM];
__device__ __align__(256) __half g_Wv[(size_t)DM * DM];
__device__ __align__(256) __half g_Q [(size_t)SEQ * DM];
__device__ __align__(256) __half g_K [(size_t)SEQ * DM];
__device__ __align__(256) __half g_VT[(size_t)DM * SEQ];
__device__ __align__(256) __half g_Sh[(size_t)SEQ * SEQ];   // fp16 scores -> probs (in place)

// ---------------- helpers ----------------
__device__ __forceinline__ uint32_t smem_u32(const void* p) {
    uint32_t a;
    asm("{ .reg .u64 t; cvta.to.shared.u64 t, %1; cvt.u32.u64 %0, t; }" : "=r"(a) : "l"(p));
    return a;
}

#define CP_ASYNC16(d, s)  asm volatile("cp.async.cg.shared.global [%0], [%1], 16;" :: "r"((uint32_t)(d)), "l"(s) : "memory")
#define CP_COMMIT()       asm volatile("cp.async.commit_group;" ::: "memory")
#define CP_WAIT2()        asm volatile("cp.async.wait_group 2;" ::: "memory")

// m16n8k16 f16 mma, fp32 accumulate (sm_80+, valid on plain sm_100 target)
__device__ __forceinline__ void mma16(float c[4], const uint32_t a[4], const uint32_t b[2]) {
    asm volatile(
        "mma.sync.aligned.m16n8k16.row.col.f32.f16.f16.f32 "
        "{%0,%1,%2,%3}, {%4,%5,%6,%7}, {%8,%9}, {%0,%1,%2,%3};\n"
        : "+f"(c[0]), "+f"(c[1]), "+f"(c[2]), "+f"(c[3])
        : "r"(a[0]), "r"(a[1]), "r"(a[2]), "r"(a[3]), "r"(b[0]), "r"(b[1]));
}

// ---------------- generic fp16 GEMM: C[m,n] = alpha * sum_k A[m,k]*B[n,k] ----------------
// Templated on WN (n-mma tiles per warp): BN = 16*WN. Warp grid 2(M) x 2(N),
// warp tile 64 x (8*WN). A:[M,K], B:[N,K] half row-major. Output fp32/fp16.
static constexpr int BM = 128, BK = 32;
static constexpr int PAD = 40;                     // halves per smem row (80B, conflict-free)
static constexpr int A_TILE_H = BM * PAD;          // 5120 halves
static constexpr int NSTG = 4;

template <int WN>
__global__ void __launch_bounds__(128, 2)
gemm_f16(void* __restrict__ Cv, const __half* __restrict__ A, const __half* __restrict__ B,
         int N, int K, float alpha, int out_half) {
    constexpr int BN = 16 * WN;
    constexpr int B_TILE_H = BN * PAD;
    constexpr int STAGE_H  = A_TILE_H + B_TILE_H;

    extern __shared__ __half smem[];
    const int tid  = threadIdx.x;
    const int wid  = tid >> 5;
    const int lane = tid & 31;
    const int wm = wid & 1;          // 2 warps along M (64 rows each)
    const int wn = wid >> 1;         // 2 warps along N (8*WN cols each)
    const int g = lane >> 2;         // 0..7
    const int t = lane & 3;          // 0..3

    // tile-order swizzle: chunks of 8 n-tiles, m-major inside a chunk -> compact waves
    const int id = blockIdx.y * gridDim.x + blockIdx.x;
    const int chunk = id / (8 * gridDim.y);
    const int rem   = id % (8 * gridDim.y);
    const int tile_m = (rem / 8) * BM;
    const int tile_n = (chunk * 8 + (rem & 7)) * BN;

    const __half* gA = A + (size_t)tile_m * K;
    const __half* gB = B + (size_t)tile_n * K;

    float acc[4][WN][4];
#pragma unroll
    for (int i = 0; i < 4; i++)
#pragma unroll
        for (int j = 0; j < WN; j++)
#pragma unroll
            for (int q = 0; q < 4; q++) acc[i][j][q] = 0.f;

    const int nst = K / BK;

    auto load_stage = [&](int stg, int kblk) {
        __half* sA = smem + (size_t)stg * STAGE_H;
        __half* sB = sA + A_TILE_H;
        const __half* pA = gA + (size_t)kblk * BK;
        const __half* pB = gB + (size_t)kblk * BK;
#pragma unroll
        for (int i = 0; i < 4; i++) {              // A: 128 rows * 4 chunks(16B)
            int c = tid + 128 * i;
            int row = c >> 2, ch = c & 3;
            CP_ASYNC16(smem_u32(sA + row * PAD + ch * 8), pA + (size_t)row * K + ch * 8);
        }
#pragma unroll
        for (int i = 0; i < WN / 2; i++) {         // B: BN rows * 4 chunks
            int c = tid + 128 * i;
            int row = c >> 2, ch = c & 3;
            CP_ASYNC16(smem_u32(sB + row * PAD + ch * 8), pB + (size_t)row * K + ch * 8);
        }
        CP_COMMIT();
    };

    load_stage(0, 0);
    load_stage(1, 1);
    load_stage(2, 2);

    for (int s = 0; s < nst; s++) {
        CP_WAIT2();              // stage s resident (<=2 newer groups pending)
        __syncthreads();

        if (s + 3 < nst) load_stage((s + 3) % NSTG, s + 3);
        else             CP_COMMIT();

        const __half* sA = smem + (size_t)(s % NSTG) * STAGE_H;
        const __half* sB = sA + A_TILE_H;

#pragma unroll
        for (int ks = 0; ks < 2; ks++) {     // two k16 steps per BK=32
            const int k0 = ks * 16 + t * 2;
            uint32_t af[4][4];
#pragma unroll
            for (int im = 0; im < 4; im++) {
                const int r = wm * 64 + im * 16 + g;
                af[im][0] = *(const uint32_t*)(sA + r * PAD + k0);
                af[im][1] = *(const uint32_t*)(sA + (r + 8) * PAD + k0);
                af[im][2] = *(const uint32_t*)(sA + r * PAD + k0 + 8);
                af[im][3] = *(const uint32_t*)(sA + (r + 8) * PAD + k0 + 8);
            }
#pragma unroll
            for (int in = 0; in < WN; in++) {
                const int n = wn * (8 * WN) + in * 8 + g;
                uint32_t bf[2];
                bf[0] = *(const uint32_t*)(sB + n * PAD + k0);
                bf[1] = *(const uint32_t*)(sB + n * PAD + k0 + 8);
#pragma unroll
                for (int im = 0; im < 4; im++) mma16(acc[im][in], af[im], bf);
            }
        }
    }

    // epilogue
#pragma unroll
    for (int im = 0; im < 4; im++) {
        const int row = tile_m + wm * 64 + im * 16 + g;
#pragma unroll
        for (int in = 0; in < WN; in++) {
            const int col = tile_n + wn * (8 * WN) + in * 8 + t * 2;
            float c0 = acc[im][in][0] * alpha, c1 = acc[im][in][1] * alpha;
            float c2 = acc[im][in][2] * alpha, c3 = acc[im][in][3] * alpha;
            if (out_half) {
                __half* C = (__half*)Cv;
                *(__half2*)(C + (size_t)row * N + col)       = __floats2half2_rn(c0, c1);
                *(__half2*)(C + (size_t)(row + 8) * N + col) = __floats2half2_rn(c2, c3);
            } else {
                float* C = (float*)Cv;
                *(float2*)(C + (size_t)row * N + col)       = make_float2(c0, c1);
                *(float2*)(C + (size_t)(row + 8) * N + col) = make_float2(c2, c3);
            }
        }
    }
}

static constexpr size_t SMEM_WN8 = (size_t)NSTG * (A_TILE_H + 128 * PAD) * 2;  // 81920 B
static constexpr size_t SMEM_WN4 = (size_t)NSTG * (A_TILE_H +  64 * PAD) * 2;  // 61440 B

// ---------------- row softmax, in place on fp16 S ----------------
__global__ void __launch_bounds__(256, 1)
softmax_rows(__half* __restrict__ S) {
    uint4* row = (uint4*)(S + (size_t)blockIdx.x * SEQ);   // 8 halves per uint4
    __shared__ float red[16];
    const int t = threadIdx.x, w = t >> 5;

    float v[32];
    float m = -1e30f;
#pragma unroll
    for (int i = 0; i < 4; i++) {                 // 1024 uint4 per row / 256 thr = 4
        uint4 u = row[t + 256 * i];
        const __half2* h = (const __half2*)&u;
#pragma unroll
        for (int j = 0; j < 4; j++) {
            float2 f = __half22float2(h[j]);
            v[i * 8 + 2 * j]     = f.x;
            v[i * 8 + 2 * j + 1] = f.y;
            m = fmaxf(m, fmaxf(f.x, f.y));
        }
    }
#pragma unroll
    for (int o = 16; o; o >>= 1) m = fmaxf(m, __shfl_xor_sync(~0u, m, o));
    if ((t & 31) == 0) red[w] = m;
    __syncthreads();
    m = red[0];
#pragma unroll
    for (int i = 1; i < 8; i++) m = fmaxf(m, red[i]);

    float s = 0.f;
#pragma unroll
    for (int i = 0; i < 32; i++) { v[i] = __expf(v[i] - m); s += v[i]; }
#pragma unroll
    for (int o = 16; o; o >>= 1) s += __shfl_xor_sync(~0u, s, o);
    if ((t & 31) == 0) red[8 + w] = s;
    __syncthreads();
    s = red[8];
#pragma unroll
    for (int i = 9; i < 16; i++) s += red[i];
    const float inv = 1.0f / s;

#pragma unroll
    for (int i = 0; i < 4; i++) {
        uint4 u;
        __half2* h = (__half2*)&u;
#pragma unroll
        for (int j = 0; j < 4; j++)
            h[j] = __floats2half2_rn(v[i * 8 + 2 * j] * inv, v[i * 8 + 2 * j + 1] * inv);
        row[t + 256 * i] = u;
    }
}

// ---------------- fp32 -> fp16 conversion ----------------
__global__ void to_half(__half* __restrict__ dst, const float* __restrict__ src, int n4) {
    int i = blockIdx.x * blockDim.x + threadIdx.x;
    if (i < n4) {
        float4 a = ((const float4*)src)[i];
        ((__half2*)dst)[2 * i]     = __floats2half2_rn(a.x, a.y);
        ((__half2*)dst)[2 * i + 1] = __floats2half2_rn(a.z, a.w);
    }
}

// ---------------- launch ----------------
extern "C" void kernel_launch(void* const* d_in, const int* in_sizes, int n_in,
                              void* d_out, int out_size) {
    const float* x  = (const float*)d_in[0];
    const float* wq = (const float*)d_in[1];
    const float* wk = (const float*)d_in[2];
    const float* wv = (const float*)d_in[3];
    float* out = (float*)d_out;

    cudaFuncSetAttribute(gemm_f16<8>, cudaFuncAttributeMaxDynamicSharedMemorySize, (int)SMEM_WN8);
    cudaFuncSetAttribute(gemm_f16<4>, cudaFuncAttributeMaxDynamicSharedMemorySize, (int)SMEM_WN4);

    __half *Xh, *Wq, *Wk, *Wv, *Q, *K, *VT, *Sh;
    cudaGetSymbolAddress((void**)&Xh, g_Xh);
    cudaGetSymbolAddress((void**)&Wq, g_Wq);
    cudaGetSymbolAddress((void**)&Wk, g_Wk);
    cudaGetSymbolAddress((void**)&Wv, g_Wv);
    cudaGetSymbolAddress((void**)&Q,  g_Q);
    cudaGetSymbolAddress((void**)&K,  g_K);
    cudaGetSymbolAddress((void**)&VT, g_VT);
    cudaGetSymbolAddress((void**)&Sh, g_Sh);

    const int nX4 = SEQ * DM / 4, nW4 = DM * DM / 4;
    to_half<<<nX4 / 256, 256>>>(Xh, x,  nX4);
    to_half<<<nW4 / 256, 256>>>(Wq, wq, nW4);
    to_half<<<nW4 / 256, 256>>>(Wk, wk, nW4);
    to_half<<<nW4 / 256, 256>>>(Wv, wv, nW4);

    // Q = Xh @ Wq^T   [8192, 2048] fp16   (BN=64: 2048 tiles -> ~1% wave waste)
    gemm_f16<4><<<dim3(DM / 64, SEQ / BM), 128, SMEM_WN4>>>(Q, Xh, Wq, DM, DM, 1.0f, 1);
    // K = Xh @ Wk^T   [8192, 2048] fp16
    gemm_f16<4><<<dim3(DM / 64, SEQ / BM), 128, SMEM_WN4>>>(K, Xh, Wk, DM, DM, 1.0f, 1);
    // VT = Wv @ Xh^T  [2048, 8192] fp16  (V computed pre-transposed)
    gemm_f16<4><<<dim3(SEQ / 64, DM / BM), 128, SMEM_WN4>>>(VT, Wv, Xh, SEQ, DM, 1.0f, 1);
    // S = (Q @ K^T) / sqrt(DM)   [8192, 8192] fp16   (BN=128: 13.84 waves, keep)
    gemm_f16<8><<<dim3(SEQ / 128, SEQ / BM), 128, SMEM_WN8>>>(Sh, Q, K, SEQ, DM,
                                                              0.022097086912079608f, 1);
    // P = softmax(S) in place (fp16)
    softmax_rows<<<SEQ, 256>>>(Sh);
    // out = P @ VT^T   [8192, 2048] fp32   (BN=64)
    gemm_f16<4><<<dim3(DM / 64, SEQ / BM), 128, SMEM_WN4>>>(out, Sh, VT, DM, SEQ, 1.0f, 0);
}